// round 12
// baseline (speedup 1.0000x reference)
#include <cuda_runtime.h>
#include <math.h>

#define LSEQ 2048
#define HDIM 1024
#define MM2  256
#define RIDGE_C 0.01f

// ---- scratch (device globals; no allocations) ----
static __device__ float g_q  [8388608];
static __device__ float g_k  [8388608];
static __device__ float g_v  [8388608];
static __device__ float g_oh [8388608];
static __device__ float g_phiq[33554432];
static __device__ float g_phik[33554432];
static __device__ float g_G  [4194304];
static __device__ float g_T  [1048576];
static __device__ float g_Wm [1048576];

// ---------------------------------------------------------------
// 128x128 tile NT GEMM: C[8192x1024] = A[8192x1024] * Bt[1024x1024]^T
// optional bias[1024] and per-row mask[8192] epilogue.
// ---------------------------------------------------------------
__device__ __forceinline__ void gemm_nt_1024(
    const float* __restrict__ A, const float* __restrict__ Bt,
    float* __restrict__ C, const float* __restrict__ bias,
    const float* __restrict__ mask)
{
    __shared__ float As[8][132], Bs[8][132];
    const int tid = threadIdx.x, bx = blockIdx.x, by = blockIdx.y;
    const int arow = tid >> 1, acol = (tid & 1) << 2;
    const float* Ap = A  + (size_t)(by * 128 + arow) * 1024 + acol;
    const float* Bp = Bt + (size_t)(bx * 128 + arow) * 1024 + acol;
    const int tx = tid & 15, ty = tid >> 4;
    float acc[8][8] = {};

    for (int kt = 0; kt < 128; kt++) {
        float4 av = *(const float4*)(Ap + kt * 8);
        float4 bv = *(const float4*)(Bp + kt * 8);
        __syncthreads();
        As[acol  ][arow] = av.x; As[acol+1][arow] = av.y;
        As[acol+2][arow] = av.z; As[acol+3][arow] = av.w;
        Bs[acol  ][arow] = bv.x; Bs[acol+1][arow] = bv.y;
        Bs[acol+2][arow] = bv.z; Bs[acol+3][arow] = bv.w;
        __syncthreads();
        #pragma unroll
        for (int k = 0; k < 8; k++) {
            float a[8], b[8]; float4 t;
            t = *(const float4*)&As[k][ty*8  ]; a[0]=t.x; a[1]=t.y; a[2]=t.z; a[3]=t.w;
            t = *(const float4*)&As[k][ty*8+4]; a[4]=t.x; a[5]=t.y; a[6]=t.z; a[7]=t.w;
            t = *(const float4*)&Bs[k][tx*8  ]; b[0]=t.x; b[1]=t.y; b[2]=t.z; b[3]=t.w;
            t = *(const float4*)&Bs[k][tx*8+4]; b[4]=t.x; b[5]=t.y; b[6]=t.z; b[7]=t.w;
            #pragma unroll
            for (int i = 0; i < 8; i++)
                #pragma unroll
                for (int j = 0; j < 8; j++)
                    acc[i][j] = fmaf(a[i], b[j], acc[i][j]);
        }
    }
    const int cb0 = bx * 128 + tx * 8;
    #pragma unroll
    for (int i = 0; i < 8; i++) {
        const int row = by * 128 + ty * 8 + i;
        const float mv = mask ? mask[row] : 1.0f;
        float* Crow = C + (size_t)row * 1024 + cb0;
        #pragma unroll
        for (int j = 0; j < 8; j += 4) {
            float4 v;
            v.x = acc[i][j]; v.y = acc[i][j+1]; v.z = acc[i][j+2]; v.w = acc[i][j+3];
            if (bias) { v.x += bias[cb0+j]; v.y += bias[cb0+j+1];
                        v.z += bias[cb0+j+2]; v.w += bias[cb0+j+3]; }
            v.x *= mv; v.y *= mv; v.z *= mv; v.w *= mv;
            *(float4*)(Crow + j) = v;
        }
    }
}

__global__ void __launch_bounds__(256) qkv_kernel(
    const float* __restrict__ x, const float* __restrict__ Wq,
    const float* __restrict__ Wk, const float* __restrict__ Wv,
    const float* __restrict__ mask)
{
    const int z = blockIdx.z;
    gemm_nt_1024(x, z==0?Wq:(z==1?Wk:Wv), z==0?g_q:(z==1?g_k:g_v),
                 nullptr, z==2?mask:nullptr);
}

__global__ void __launch_bounds__(256) final_kernel(
    const float* __restrict__ Wo, const float* __restrict__ bo,
    const float* __restrict__ mask, float* __restrict__ out)
{
    gemm_nt_1024(g_oh, Wo, out, bo, mask);
}

// ---------------------------------------------------------------
// RFF: per (bh, 128-row l tile, isK). proj = X(128x64) @ W(64x128) + b
// Phi[:,m]=s*cos, Phi[:,128+m]=s*sin ; PhiK masked per row.
// ---------------------------------------------------------------
__global__ void __launch_bounds__(256) rff_kernel(
    const float* __restrict__ rffW, const float* __restrict__ rffb,
    const float* __restrict__ mask)
{
    extern __shared__ float sm[];
    float* Ws = sm;            // [64][128]
    float* Xs = sm + 8192;     // [128][65]
    __shared__ float bsh[128], msh[128];

    const int bh = blockIdx.x, b = bh >> 4, h = bh & 15;
    const int lt = blockIdx.y, isK = blockIdx.z;
    const float* Xg = (isK ? g_k : g_q) + (size_t)(b*LSEQ + lt*128)*HDIM + h*64;
    float* Phi = (isK ? g_phik : g_phiq) + ((size_t)bh*LSEQ + lt*128)*MM2;

    const int tid = threadIdx.x;
    for (int i = tid; i < 8192; i += 256) Ws[i] = rffW[h*8192 + i];
    if (tid < 128) {
        bsh[tid] = rffb[h*128 + tid];
        msh[tid] = isK ? mask[b*LSEQ + lt*128 + tid] : 1.0f;
    }
    for (int i = tid; i < 8192; i += 256) {
        const int l = i >> 6, d = i & 63;
        Xs[l*65 + d] = Xg[(size_t)l*HDIM + d];
    }
    __syncthreads();

    const int tx = tid & 15, ty = tid >> 4;
    float acc[8][8];
    #pragma unroll
    for (int i = 0; i < 8; i++)
        #pragma unroll
        for (int j = 0; j < 8; j++) acc[i][j] = bsh[tx + 16*j];

    for (int d = 0; d < 64; d++) {
        float a[8], w[8];
        #pragma unroll
        for (int i = 0; i < 8; i++) a[i] = Xs[(ty + 16*i)*65 + d];
        #pragma unroll
        for (int j = 0; j < 8; j++) w[j] = Ws[d*128 + tx + 16*j];
        #pragma unroll
        for (int i = 0; i < 8; i++)
            #pragma unroll
            for (int j = 0; j < 8; j++)
                acc[i][j] = fmaf(a[i], w[j], acc[i][j]);
    }
    const float sc = 0.0883883476483184f;  // 1/sqrt(128)
    #pragma unroll
    for (int i = 0; i < 8; i++) {
        const int l = ty + 16*i;
        const float mv = msh[l];
        float* row = Phi + (size_t)l*MM2;
        #pragma unroll
        for (int j = 0; j < 8; j++) {
            float s, c;
            sincosf(acc[i][j], &s, &c);
            row[tx + 16*j]       = sc * c * mv;
            row[128 + tx + 16*j] = sc * s * mv;
        }
    }
}

// ---------------------------------------------------------------
// Gram: G[bh] = PhiK^T PhiK, 256x256, K=2048. grid (2,2,64)
// ---------------------------------------------------------------
__global__ void __launch_bounds__(256) gram_kernel()
{
    __shared__ float As[16][132], Bs[16][132];
    const int bh = blockIdx.z;
    const float* A = g_phik + (size_t)bh * LSEQ * MM2;
    const int m0 = blockIdx.y * 128, n0 = blockIdx.x * 128;
    const int tid = threadIdx.x;
    const int r = tid >> 4, c = (tid & 15) << 3;
    const int tx = tid & 15, ty = tid >> 4;
    float acc[8][8] = {};

    for (int kt = 0; kt < LSEQ/16; kt++) {
        const float* Arow = A + (size_t)(kt*16 + r) * MM2;
        float4 a1 = *(const float4*)(Arow + m0 + c);
        float4 a2 = *(const float4*)(Arow + m0 + c + 4);
        float4 b1 = *(const float4*)(Arow + n0 + c);
        float4 b2 = *(const float4*)(Arow + n0 + c + 4);
        __syncthreads();
        *(float4*)&As[r][c] = a1; *(float4*)&As[r][c+4] = a2;
        *(float4*)&Bs[r][c] = b1; *(float4*)&Bs[r][c+4] = b2;
        __syncthreads();
        #pragma unroll
        for (int k = 0; k < 16; k++) {
            float a[8], b[8]; float4 t;
            t = *(const float4*)&As[k][ty*8  ]; a[0]=t.x; a[1]=t.y; a[2]=t.z; a[3]=t.w;
            t = *(const float4*)&As[k][ty*8+4]; a[4]=t.x; a[5]=t.y; a[6]=t.z; a[7]=t.w;
            t = *(const float4*)&Bs[k][tx*8  ]; b[0]=t.x; b[1]=t.y; b[2]=t.z; b[3]=t.w;
            t = *(const float4*)&Bs[k][tx*8+4]; b[4]=t.x; b[5]=t.y; b[6]=t.z; b[7]=t.w;
            #pragma unroll
            for (int i = 0; i < 8; i++)
                #pragma unroll
                for (int j = 0; j < 8; j++)
                    acc[i][j] = fmaf(a[i], b[j], acc[i][j]);
        }
    }
    float* Cb = g_G + (size_t)bh * MM2 * MM2;
    #pragma unroll
    for (int i = 0; i < 8; i++) {
        float* Crow = Cb + (size_t)(m0 + ty*8 + i) * MM2 + n0 + tx*8;
        float4 v0, v1;
        v0.x=acc[i][0]; v0.y=acc[i][1]; v0.z=acc[i][2]; v0.w=acc[i][3];
        v1.x=acc[i][4]; v1.y=acc[i][5]; v1.z=acc[i][6]; v1.w=acc[i][7];
        *(float4*)Crow = v0; *(float4*)(Crow+4) = v1;
    }
}

// ---------------------------------------------------------------
// T[bh] = PhiK^T V_w, 256x64, K=2048. grid (2,64)
// ---------------------------------------------------------------
__global__ void __launch_bounds__(256) tmat_kernel()
{
    __shared__ float As[16][132], Bs[16][68];
    const int bh = blockIdx.y, b = bh >> 4, h = bh & 15;
    const int m0 = blockIdx.x * 128;
    const float* A = g_phik + (size_t)bh * LSEQ * MM2;
    const float* V = g_v + (size_t)b * LSEQ * HDIM + h * 64;
    const int tid = threadIdx.x;
    const int r = tid >> 4, c = (tid & 15) << 3, cb = (tid & 15) << 2;
    const int md = tid >> 4, d0 = (tid & 15) << 2;
    float acc[8][4] = {};

    for (int kt = 0; kt < LSEQ/16; kt++) {
        const float* Arow = A + (size_t)(kt*16 + r) * MM2 + m0;
        float4 a1 = *(const float4*)(Arow + c);
        float4 a2 = *(const float4*)(Arow + c + 4);
        float4 b1 = *(const float4*)(V + (size_t)(kt*16 + r) * HDIM + cb);
        __syncthreads();
        *(float4*)&As[r][c] = a1; *(float4*)&As[r][c+4] = a2;
        *(float4*)&Bs[r][cb] = b1;
        __syncthreads();
        #pragma unroll
        for (int k = 0; k < 16; k++) {
            float a[8]; float4 t;
            t = *(const float4*)&As[k][md*8  ]; a[0]=t.x; a[1]=t.y; a[2]=t.z; a[3]=t.w;
            t = *(const float4*)&As[k][md*8+4]; a[4]=t.x; a[5]=t.y; a[6]=t.z; a[7]=t.w;
            float4 bb = *(const float4*)&Bs[k][d0];
            #pragma unroll
            for (int i = 0; i < 8; i++) {
                acc[i][0] = fmaf(a[i], bb.x, acc[i][0]);
                acc[i][1] = fmaf(a[i], bb.y, acc[i][1]);
                acc[i][2] = fmaf(a[i], bb.z, acc[i][2]);
                acc[i][3] = fmaf(a[i], bb.w, acc[i][3]);
            }
        }
    }
    float* C = g_T + (size_t)bh * MM2 * 64;
    #pragma unroll
    for (int i = 0; i < 8; i++) {
        float4 v; v.x=acc[i][0]; v.y=acc[i][1]; v.z=acc[i][2]; v.w=acc[i][3];
        *(float4*)(C + (size_t)(m0 + md*8 + i) * 64 + d0) = v;
    }
}

// ---------------------------------------------------------------
// Per-(b,h): Cholesky (packed lower in smem) + L y = T, L^T x = y (64 RHS).
// dyn smem = 32896*4 + 16384*4 = 197120 B. grid 64, one wave.
// ---------------------------------------------------------------
__global__ void __launch_bounds__(256) chol_solve_kernel()
{
    extern __shared__ float sm[];
    float* Lp = sm;            // packed lower: Lp[i*(i+1)/2 + j]
    float* Y  = sm + 32896;    // [256][64]
    __shared__ float sdiag, sinv;
    const int bh = blockIdx.x, tid = threadIdx.x;
    const float* G  = g_G + (size_t)bh * 65536;
    const float* Tg = g_T + (size_t)bh * 16384;

    for (int i = 0; i < 256; i++) {
        const int ro = i*(i+1)/2;
        for (int j = tid; j <= i; j += 256)
            Lp[ro + j] = G[i*256 + j] + ((j == i) ? RIDGE_C : 0.0f);
    }
    for (int t = tid; t < 16384; t += 256) Y[t] = Tg[t];
    __syncthreads();

    // left-looking Cholesky, column j; thread tid owns row j+tid
    for (int j = 0; j < 256; j++) {
        const int r = j + tid, jo = j*(j+1)/2;
        float a = 0.0f; int ro = 0;
        if (r < 256) {
            ro = r*(r+1)/2;
            float a0=0.f, a1=0.f, a2=0.f, a3=0.f; int c = 0;
            for (; c + 4 <= j; c += 4) {
                a0 = fmaf(Lp[ro+c  ], Lp[jo+c  ], a0);
                a1 = fmaf(Lp[ro+c+1], Lp[jo+c+1], a1);
                a2 = fmaf(Lp[ro+c+2], Lp[jo+c+2], a2);
                a3 = fmaf(Lp[ro+c+3], Lp[jo+c+3], a3);
            }
            for (; c < j; c++) a0 = fmaf(Lp[ro+c], Lp[jo+c], a0);
            a = Lp[ro + j] - ((a0 + a1) + (a2 + a3));
        }
        if (tid == 0) { float s = sqrtf(a); sdiag = s; sinv = 1.0f / s; }
        __syncthreads();
        if (r < 256) Lp[ro + j] = (tid == 0) ? sdiag : a * sinv;
        __syncthreads();
    }

    const int d = tid & 63, io = tid >> 6;
    // forward: L y = T (8-col blocked)
    for (int jb = 0; jb < 256; jb += 8) {
        for (int jj = 0; jj < 8; jj++) {
            const int j = jb + jj;
            if (tid < 64) {
                const int jo = j*(j+1)/2;
                float yv = Y[j*64 + tid];
                for (int c = jb; c < j; c++)
                    yv = fmaf(-Lp[jo + c], Y[c*64 + tid], yv);
                Y[j*64 + tid] = yv / Lp[jo + j];
            }
            __syncthreads();
        }
        for (int i = jb + 8 + io; i < 256; i += 4) {
            const int ro = i*(i+1)/2 + jb;
            float a = Y[i*64 + d];
            #pragma unroll
            for (int jj = 0; jj < 8; jj++)
                a = fmaf(-Lp[ro + jj], Y[(jb+jj)*64 + d], a);
            Y[i*64 + d] = a;
        }
        __syncthreads();
    }
    // backward: L^T x = y (8-row blocked, bottom-up)
    for (int ib = 248; ib >= 0; ib -= 8) {
        for (int jj = 7; jj >= 0; jj--) {
            const int j = ib + jj;
            if (tid < 64) {
                float yv = Y[j*64 + tid];
                for (int c = j + 1; c < ib + 8; c++)
                    yv = fmaf(-Lp[c*(c+1)/2 + j], Y[c*64 + tid], yv);
                Y[j*64 + tid] = yv / Lp[j*(j+1)/2 + j];
            }
            __syncthreads();
        }
        for (int i = io; i < ib; i += 4) {
            float a = Y[i*64 + d];
            #pragma unroll
            for (int jj = 0; jj < 8; jj++) {
                const int k = ib + jj;
                a = fmaf(-Lp[k*(k+1)/2 + i], Y[k*64 + d], a);
            }
            Y[i*64 + d] = a;
        }
        __syncthreads();
    }
    float* Wout = g_Wm + (size_t)bh * 16384;
    for (int t = tid; t < 16384; t += 256) Wout[t] = Y[t];
}

// ---------------------------------------------------------------
// out_heads = PhiQ(2048x256) @ W(256x64) per bh -> g_oh[(b,l),(h*64+d)]
// grid (16, 64)
// ---------------------------------------------------------------
__global__ void __launch_bounds__(256) outproj_kernel()
{
    __shared__ float As[16][132], Bs[16][68];
    const int bh = blockIdx.y, b = bh >> 4, h = bh & 15;
    const int l0 = blockIdx.x * 128;
    const float* A  = g_phiq + ((size_t)bh*LSEQ + l0) * MM2;
    const float* Wp = g_Wm + (size_t)bh * 16384;
    const int tid = threadIdx.x;
    const int lr = tid >> 1, kq = (tid & 1) << 3;
    const int rb = tid >> 4, cb = (tid & 15) << 2;
    const int lm = tid >> 4, d0 = (tid & 15) << 2;
    float acc[8][4] = {};

    for (int kt = 0; kt < MM2/16; kt++) {
        float4 a1 = *(const float4*)(A + (size_t)lr*MM2 + kt*16 + kq);
        float4 a2 = *(const float4*)(A + (size_t)lr*MM2 + kt*16 + kq + 4);
        float4 b1 = *(const float4*)(Wp + (size_t)(kt*16 + rb)*64 + cb);
        __syncthreads();
        As[kq  ][lr] = a1.x; As[kq+1][lr] = a1.y;
        As[kq+2][lr] = a1.z; As[kq+3][lr] = a1.w;
        As[kq+4][lr] = a2.x; As[kq+5][lr] = a2.y;
        As[kq+6][lr] = a2.z; As[kq+7][lr] = a2.w;
        *(float4*)&Bs[rb][cb] = b1;
        __syncthreads();
        #pragma unroll
        for (int k = 0; k < 16; k++) {
            float a[8]; float4 t;
            t = *(const float4*)&As[k][lm*8  ]; a[0]=t.x; a[1]=t.y; a[2]=t.z; a[3]=t.w;
            t = *(const float4*)&As[k][lm*8+4]; a[4]=t.x; a[5]=t.y; a[6]=t.z; a[7]=t.w;
            float4 bb = *(const float4*)&Bs[k][d0];
            #pragma unroll
            for (int i = 0; i < 8; i++) {
                acc[i][0] = fmaf(a[i], bb.x, acc[i][0]);
                acc[i][1] = fmaf(a[i], bb.y, acc[i][1]);
                acc[i][2] = fmaf(a[i], bb.z, acc[i][2]);
                acc[i][3] = fmaf(a[i], bb.w, acc[i][3]);
            }
        }
    }
    #pragma unroll
    for (int i = 0; i < 8; i++) {
        float4 v; v.x=acc[i][0]; v.y=acc[i][1]; v.z=acc[i][2]; v.w=acc[i][3];
        *(float4*)(g_oh + (size_t)(b*LSEQ + l0 + lm*8 + i)*HDIM + h*64 + d0) = v;
    }
}

extern "C" void kernel_launch(void* const* d_in, const int* in_sizes, int n_in,
                              void* d_out, int out_size)
{
    const float* x    = (const float*)d_in[0];
    const float* mask = (const float*)d_in[2];
    const float* Wq   = (const float*)d_in[3];
    const float* Wk   = (const float*)d_in[4];
    const float* Wv   = (const float*)d_in[5];
    const float* Wo   = (const float*)d_in[6];
    const float* bo   = (const float*)d_in[7];
    const float* rW   = (const float*)d_in[8];
    const float* rb   = (const float*)d_in[9];
    float* out = (float*)d_out;

    cudaFuncSetAttribute(rff_kernel, cudaFuncAttributeMaxDynamicSharedMemorySize, 66048);
    cudaFuncSetAttribute(chol_solve_kernel, cudaFuncAttributeMaxDynamicSharedMemorySize, 197120);

    qkv_kernel<<<dim3(8, 64, 3), 256>>>(x, Wq, Wk, Wv, mask);
    rff_kernel<<<dim3(64, 16, 2), 256, 66048>>>(rW, rb, mask);
    gram_kernel<<<dim3(2, 2, 64), 256>>>();
    tmat_kernel<<<dim3(2, 64), 256>>>();
    chol_solve_kernel<<<64, 256, 197120>>>();
    outproj_kernel<<<dim3(16, 64), 256>>>();
    final_kernel<<<dim3(8, 64), 256>>>(Wo, bo, mask, out);
}

// round 13
// speedup vs baseline: 1.0538x; 1.0538x over previous
#include <cuda_runtime.h>
#include <math.h>

#define LSEQ 2048
#define HDIM 1024
#define MM2  256
#define RIDGE_C 0.01f

typedef unsigned long long ull;

// ---- packed f32x2 helpers (FFMA2 is PTX-only; ptxas never auto-fuses) ----
__device__ __forceinline__ ull bcast2(float x) {
    ull r; unsigned u = __float_as_uint(x);
    asm("mov.b64 %0, {%1, %1};" : "=l"(r) : "r"(u));
    return r;
}
__device__ __forceinline__ void ffma2(ull& d, ull a, ull b) {
    asm("fma.rn.f32x2 %0, %1, %2, %0;" : "+l"(d) : "l"(a), "l"(b));
}
__device__ __forceinline__ void unpk2(ull v, float& lo, float& hi) {
    unsigned a, b;
    asm("mov.b64 {%0, %1}, %2;" : "=r"(a), "=r"(b) : "l"(v));
    lo = __uint_as_float(a); hi = __uint_as_float(b);
}

// ---- scratch (device globals; no allocations) ----
static __device__ float g_q  [8388608];
static __device__ float g_k  [8388608];
static __device__ float g_v  [8388608];
static __device__ float g_oh [8388608];
static __device__ float g_phiq[33554432];
static __device__ float g_phik[33554432];
static __device__ float g_G  [4194304];
static __device__ float g_Tp [4194304];   // 4 k-split partials of T
static __device__ float g_Wm [1048576];

// ---------------------------------------------------------------
// 128x128 tile NT GEMM: C[8192x1024] = A[8192x1024] * Bt[1024x1024]^T
// f32x2 accumulators, register prefetch of next K tile.
// optional bias[1024] and per-row mask[8192] epilogue.
// ---------------------------------------------------------------
__device__ __forceinline__ void gemm_nt_1024(
    const float* __restrict__ A, const float* __restrict__ Bt,
    float* __restrict__ C, const float* __restrict__ bias,
    const float* __restrict__ mask)
{
    __shared__ __align__(16) float As[8][132], Bs[8][132];
    const int tid = threadIdx.x, bx = blockIdx.x, by = blockIdx.y;
    const int arow = tid >> 1, acol = (tid & 1) << 2;
    const float* Ap = A  + (size_t)(by * 128 + arow) * 1024 + acol;
    const float* Bp = Bt + (size_t)(bx * 128 + arow) * 1024 + acol;
    const int tx = tid & 15, ty = tid >> 4;

    ull accp[8][4];
    #pragma unroll
    for (int i = 0; i < 8; i++)
        #pragma unroll
        for (int j = 0; j < 4; j++) accp[i][j] = 0ull;

    float4 av = *(const float4*)Ap;
    float4 bv = *(const float4*)Bp;

    for (int kt = 0; kt < 128; kt++) {
        __syncthreads();
        As[acol  ][arow] = av.x; As[acol+1][arow] = av.y;
        As[acol+2][arow] = av.z; As[acol+3][arow] = av.w;
        Bs[acol  ][arow] = bv.x; Bs[acol+1][arow] = bv.y;
        Bs[acol+2][arow] = bv.z; Bs[acol+3][arow] = bv.w;
        __syncthreads();
        if (kt < 127) {
            av = *(const float4*)(Ap + (size_t)(kt + 1) * 8);
            bv = *(const float4*)(Bp + (size_t)(kt + 1) * 8);
        }
        #pragma unroll
        for (int k = 0; k < 8; k++) {
            float4 t0 = *(const float4*)&As[k][ty*8];
            float4 t1 = *(const float4*)&As[k][ty*8+4];
            ulonglong2 b0 = *(const ulonglong2*)&Bs[k][tx*8];
            ulonglong2 b1 = *(const ulonglong2*)&Bs[k][tx*8+4];
            float a[8] = {t0.x,t0.y,t0.z,t0.w,t1.x,t1.y,t1.z,t1.w};
            #pragma unroll
            for (int i = 0; i < 8; i++) {
                ull ap = bcast2(a[i]);
                ffma2(accp[i][0], ap, b0.x);
                ffma2(accp[i][1], ap, b0.y);
                ffma2(accp[i][2], ap, b1.x);
                ffma2(accp[i][3], ap, b1.y);
            }
        }
    }

    const int cb0 = bx * 128 + tx * 8;
    #pragma unroll
    for (int i = 0; i < 8; i++) {
        const int row = by * 128 + ty * 8 + i;
        const float mv = mask ? mask[row] : 1.0f;
        float vals[8];
        #pragma unroll
        for (int jp = 0; jp < 4; jp++) unpk2(accp[i][jp], vals[2*jp], vals[2*jp+1]);
        float* Crow = C + (size_t)row * 1024 + cb0;
        #pragma unroll
        for (int j = 0; j < 8; j += 4) {
            float4 v;
            v.x = vals[j]; v.y = vals[j+1]; v.z = vals[j+2]; v.w = vals[j+3];
            if (bias) { v.x += bias[cb0+j]; v.y += bias[cb0+j+1];
                        v.z += bias[cb0+j+2]; v.w += bias[cb0+j+3]; }
            v.x *= mv; v.y *= mv; v.z *= mv; v.w *= mv;
            *(float4*)(Crow + j) = v;
        }
    }
}

__global__ void __launch_bounds__(256) qkv_kernel(
    const float* __restrict__ x, const float* __restrict__ Wq,
    const float* __restrict__ Wk, const float* __restrict__ Wv,
    const float* __restrict__ mask)
{
    const int z = blockIdx.z;
    gemm_nt_1024(x, z==0?Wq:(z==1?Wk:Wv), z==0?g_q:(z==1?g_k:g_v),
                 nullptr, z==2?mask:nullptr);
}

__global__ void __launch_bounds__(256) final_kernel(
    const float* __restrict__ Wo, const float* __restrict__ bo,
    const float* __restrict__ mask, float* __restrict__ out)
{
    gemm_nt_1024(g_oh, Wo, out, bo, mask);
}

// ---------------------------------------------------------------
// RFF: per (bh, 128-row l tile, isK). proj = X(128x64) @ W(64x128) + b
// Phi[:,m]=s*cos, Phi[:,128+m]=s*sin ; PhiK masked per row.
// ---------------------------------------------------------------
__global__ void __launch_bounds__(256) rff_kernel(
    const float* __restrict__ rffW, const float* __restrict__ rffb,
    const float* __restrict__ mask)
{
    extern __shared__ float sm[];
    float* Ws = sm;            // [64][128]
    float* Xs = sm + 8192;     // [128][65]
    __shared__ float bsh[128], msh[128];

    const int bh = blockIdx.x, b = bh >> 4, h = bh & 15;
    const int lt = blockIdx.y, isK = blockIdx.z;
    const float* Xg = (isK ? g_k : g_q) + (size_t)(b*LSEQ + lt*128)*HDIM + h*64;
    float* Phi = (isK ? g_phik : g_phiq) + ((size_t)bh*LSEQ + lt*128)*MM2;

    const int tid = threadIdx.x;
    for (int i = tid; i < 8192; i += 256) Ws[i] = rffW[h*8192 + i];
    if (tid < 128) {
        bsh[tid] = rffb[h*128 + tid];
        msh[tid] = isK ? mask[b*LSEQ + lt*128 + tid] : 1.0f;
    }
    for (int i = tid; i < 8192; i += 256) {
        const int l = i >> 6, d = i & 63;
        Xs[l*65 + d] = Xg[(size_t)l*HDIM + d];
    }
    __syncthreads();

    const int tx = tid & 15, ty = tid >> 4;
    float acc[8][8];
    #pragma unroll
    for (int i = 0; i < 8; i++)
        #pragma unroll
        for (int j = 0; j < 8; j++) acc[i][j] = bsh[tx + 16*j];

    for (int d = 0; d < 64; d++) {
        float a[8], w[8];
        #pragma unroll
        for (int i = 0; i < 8; i++) a[i] = Xs[(ty + 16*i)*65 + d];
        #pragma unroll
        for (int j = 0; j < 8; j++) w[j] = Ws[d*128 + tx + 16*j];
        #pragma unroll
        for (int i = 0; i < 8; i++)
            #pragma unroll
            for (int j = 0; j < 8; j++)
                acc[i][j] = fmaf(a[i], w[j], acc[i][j]);
    }
    const float sc = 0.0883883476483184f;  // 1/sqrt(128)
    #pragma unroll
    for (int i = 0; i < 8; i++) {
        const int l = ty + 16*i;
        const float mv = msh[l];
        float* row = Phi + (size_t)l*MM2;
        #pragma unroll
        for (int j = 0; j < 8; j++) {
            float s, c;
            sincosf(acc[i][j], &s, &c);
            row[tx + 16*j]       = sc * c * mv;
            row[128 + tx + 16*j] = sc * s * mv;
        }
    }
}

// ---------------------------------------------------------------
// Gram: G[bh] = PhiK^T PhiK, 256x256, K=2048. grid (2,2,64)
// f32x2 accumulators + register prefetch.
// ---------------------------------------------------------------
__global__ void __launch_bounds__(256) gram_kernel()
{
    __shared__ __align__(16) float As[16][132], Bs[16][132];
    const int bh = blockIdx.z;
    const float* A = g_phik + (size_t)bh * LSEQ * MM2;
    const int m0 = blockIdx.y * 128, n0 = blockIdx.x * 128;
    const int tid = threadIdx.x;
    const int r = tid >> 4, c = (tid & 15) << 3;
    const int tx = tid & 15, ty = tid >> 4;

    ull accp[8][4];
    #pragma unroll
    for (int i = 0; i < 8; i++)
        #pragma unroll
        for (int j = 0; j < 4; j++) accp[i][j] = 0ull;

    const float* Arow = A + (size_t)r * MM2;
    float4 a1 = *(const float4*)(Arow + m0 + c);
    float4 a2 = *(const float4*)(Arow + m0 + c + 4);
    float4 b1 = *(const float4*)(Arow + n0 + c);
    float4 b2 = *(const float4*)(Arow + n0 + c + 4);

    for (int kt = 0; kt < LSEQ/16; kt++) {
        __syncthreads();
        *(float4*)&As[r][c] = a1; *(float4*)&As[r][c+4] = a2;
        *(float4*)&Bs[r][c] = b1; *(float4*)&Bs[r][c+4] = b2;
        __syncthreads();
        if (kt < LSEQ/16 - 1) {
            const float* An = A + (size_t)((kt+1)*16 + r) * MM2;
            a1 = *(const float4*)(An + m0 + c);
            a2 = *(const float4*)(An + m0 + c + 4);
            b1 = *(const float4*)(An + n0 + c);
            b2 = *(const float4*)(An + n0 + c + 4);
        }
        #pragma unroll
        for (int k = 0; k < 16; k++) {
            float4 t0 = *(const float4*)&As[k][ty*8];
            float4 t1 = *(const float4*)&As[k][ty*8+4];
            ulonglong2 p0 = *(const ulonglong2*)&Bs[k][tx*8];
            ulonglong2 p1 = *(const ulonglong2*)&Bs[k][tx*8+4];
            float a[8] = {t0.x,t0.y,t0.z,t0.w,t1.x,t1.y,t1.z,t1.w};
            #pragma unroll
            for (int i = 0; i < 8; i++) {
                ull ap = bcast2(a[i]);
                ffma2(accp[i][0], ap, p0.x);
                ffma2(accp[i][1], ap, p0.y);
                ffma2(accp[i][2], ap, p1.x);
                ffma2(accp[i][3], ap, p1.y);
            }
        }
    }
    float* Cb = g_G + (size_t)bh * MM2 * MM2;
    #pragma unroll
    for (int i = 0; i < 8; i++) {
        float vals[8];
        #pragma unroll
        for (int jp = 0; jp < 4; jp++) unpk2(accp[i][jp], vals[2*jp], vals[2*jp+1]);
        float* Crow = Cb + (size_t)(m0 + ty*8 + i) * MM2 + n0 + tx*8;
        float4 v0, v1;
        v0.x=vals[0]; v0.y=vals[1]; v0.z=vals[2]; v0.w=vals[3];
        v1.x=vals[4]; v1.y=vals[5]; v1.z=vals[6]; v1.w=vals[7];
        *(float4*)Crow = v0; *(float4*)(Crow+4) = v1;
    }
}

// ---------------------------------------------------------------
// T partials: g_Tp[kz][bh] += PhiK^T V_w over 512-row K chunk.
// grid (2, 64, 4); summed in chol_solve's T load.
// ---------------------------------------------------------------
__global__ void __launch_bounds__(256) tmat_kernel()
{
    __shared__ __align__(16) float As[16][132], Bs[16][68];
    const int bh = blockIdx.y, b = bh >> 4, h = bh & 15;
    const int m0 = blockIdx.x * 128, kz = blockIdx.z;
    const float* A = g_phik + (size_t)bh * LSEQ * MM2;
    const float* V = g_v + (size_t)b * LSEQ * HDIM + h * 64;
    const int tid = threadIdx.x;
    const int r = tid >> 4, c = (tid & 15) << 3, cb = (tid & 15) << 2;
    const int md = tid >> 4, d0 = (tid & 15) << 2;
    const int kt0 = kz * 32, kt1 = kt0 + 32;

    ull accp[8][2];
    #pragma unroll
    for (int i = 0; i < 8; i++) { accp[i][0] = 0ull; accp[i][1] = 0ull; }

    const float* Ar = A + (size_t)(kt0*16 + r) * MM2 + m0;
    float4 a1 = *(const float4*)(Ar + c);
    float4 a2 = *(const float4*)(Ar + c + 4);
    float4 b1 = *(const float4*)(V + (size_t)(kt0*16 + r) * HDIM + cb);

    for (int kt = kt0; kt < kt1; kt++) {
        __syncthreads();
        *(float4*)&As[r][c] = a1; *(float4*)&As[r][c+4] = a2;
        *(float4*)&Bs[r][cb] = b1;
        __syncthreads();
        if (kt < kt1 - 1) {
            const float* An = A + (size_t)((kt+1)*16 + r) * MM2 + m0;
            a1 = *(const float4*)(An + c);
            a2 = *(const float4*)(An + c + 4);
            b1 = *(const float4*)(V + (size_t)((kt+1)*16 + r) * HDIM + cb);
        }
        #pragma unroll
        for (int k = 0; k < 16; k++) {
            float4 t0 = *(const float4*)&As[k][md*8];
            float4 t1 = *(const float4*)&As[k][md*8+4];
            ulonglong2 bb = *(const ulonglong2*)&Bs[k][d0];
            float a[8] = {t0.x,t0.y,t0.z,t0.w,t1.x,t1.y,t1.z,t1.w};
            #pragma unroll
            for (int i = 0; i < 8; i++) {
                ull ap = bcast2(a[i]);
                ffma2(accp[i][0], ap, bb.x);
                ffma2(accp[i][1], ap, bb.y);
            }
        }
    }
    float* C = g_Tp + (size_t)kz * 1048576 + (size_t)bh * 16384;
    #pragma unroll
    for (int i = 0; i < 8; i++) {
        float4 v;
        unpk2(accp[i][0], v.x, v.y);
        unpk2(accp[i][1], v.z, v.w);
        *(float4*)(C + (size_t)(m0 + md*8 + i) * 64 + d0) = v;
    }
}

// ---------------------------------------------------------------
// Per-(b,h): Cholesky (packed lower in smem) + L y = T, L^T x = y (64 RHS).
// dyn smem = 32896*4 + 16384*4 = 197120 B. grid 64.
// ---------------------------------------------------------------
__global__ void __launch_bounds__(256) chol_solve_kernel()
{
    extern __shared__ float sm[];
    float* Lp = sm;            // packed lower: Lp[i*(i+1)/2 + j]
    float* Y  = sm + 32896;    // [256][64]
    __shared__ float sdiag, sinv;
    const int bh = blockIdx.x, tid = threadIdx.x;
    const float* G  = g_G + (size_t)bh * 65536;
    const float* T0 = g_Tp + (size_t)bh * 16384;

    for (int i = 0; i < 256; i++) {
        const int ro = i*(i+1)/2;
        for (int j = tid; j <= i; j += 256)
            Lp[ro + j] = G[i*256 + j] + ((j == i) ? RIDGE_C : 0.0f);
    }
    for (int t = tid; t < 16384; t += 256)
        Y[t] = (T0[t] + T0[t + 1048576]) + (T0[t + 2097152] + T0[t + 3145728]);
    __syncthreads();

    // left-looking Cholesky, column j; thread tid owns row j+tid
    for (int j = 0; j < 256; j++) {
        const int r = j + tid, jo = j*(j+1)/2;
        float a = 0.0f; int ro = 0;
        if (r < 256) {
            ro = r*(r+1)/2;
            float a0=0.f, a1=0.f, a2=0.f, a3=0.f; int c = 0;
            for (; c + 4 <= j; c += 4) {
                a0 = fmaf(Lp[ro+c  ], Lp[jo+c  ], a0);
                a1 = fmaf(Lp[ro+c+1], Lp[jo+c+1], a1);
                a2 = fmaf(Lp[ro+c+2], Lp[jo+c+2], a2);
                a3 = fmaf(Lp[ro+c+3], Lp[jo+c+3], a3);
            }
            for (; c < j; c++) a0 = fmaf(Lp[ro+c], Lp[jo+c], a0);
            a = Lp[ro + j] - ((a0 + a1) + (a2 + a3));
        }
        if (tid == 0) { float s = sqrtf(a); sdiag = s; sinv = 1.0f / s; }
        __syncthreads();
        if (r < 256) Lp[ro + j] = (tid == 0) ? sdiag : a * sinv;
        __syncthreads();
    }

    const int d = tid & 63, io = tid >> 6;
    // forward: L y = T (8-col blocked)
    for (int jb = 0; jb < 256; jb += 8) {
        for (int jj = 0; jj < 8; jj++) {
            const int j = jb + jj;
            if (tid < 64) {
                const int jo = j*(j+1)/2;
                float yv = Y[j*64 + tid];
                for (int c = jb; c < j; c++)
                    yv = fmaf(-Lp[jo + c], Y[c*64 + tid], yv);
                Y[j*64 + tid] = yv / Lp[jo + j];
            }
            __syncthreads();
        }
        for (int i = jb + 8 + io; i < 256; i += 4) {
            const int ro = i*(i+1)/2 + jb;
            float a = Y[i*64 + d];
            #pragma unroll
            for (int jj = 0; jj < 8; jj++)
                a = fmaf(-Lp[ro + jj], Y[(jb+jj)*64 + d], a);
            Y[i*64 + d] = a;
        }
        __syncthreads();
    }
    // backward: L^T x = y (8-row blocked, bottom-up)
    for (int ib = 248; ib >= 0; ib -= 8) {
        for (int jj = 7; jj >= 0; jj--) {
            const int j = ib + jj;
            if (tid < 64) {
                float yv = Y[j*64 + tid];
                for (int c = j + 1; c < ib + 8; c++)
                    yv = fmaf(-Lp[c*(c+1)/2 + j], Y[c*64 + tid], yv);
                Y[j*64 + tid] = yv / Lp[j*(j+1)/2 + j];
            }
            __syncthreads();
        }
        for (int i = io; i < ib; i += 4) {
            float a = Y[i*64 + d];
            #pragma unroll
            for (int jj = 0; jj < 8; jj++) {
                const int k = ib + jj;
                a = fmaf(-Lp[k*(k+1)/2 + i], Y[k*64 + d], a);
            }
            Y[i*64 + d] = a;
        }
        __syncthreads();
    }
    float* Wout = g_Wm + (size_t)bh * 16384;
    for (int t = tid; t < 16384; t += 256) Wout[t] = Y[t];
}

// ---------------------------------------------------------------
// out_heads = PhiQ(2048x256) @ W(256x64) per bh -> g_oh[(b,l),(h*64+d)]
// grid (16, 64). f32x2 accumulators + register prefetch.
// ---------------------------------------------------------------
__global__ void __launch_bounds__(256) outproj_kernel()
{
    __shared__ __align__(16) float As[16][132], Bs[16][68];
    const int bh = blockIdx.y, b = bh >> 4, h = bh & 15;
    const int l0 = blockIdx.x * 128;
    const float* A  = g_phiq + ((size_t)bh*LSEQ + l0) * MM2;
    const float* Wp = g_Wm + (size_t)bh * 16384;
    const int tid = threadIdx.x;
    const int lr = tid >> 1, kq = (tid & 1) << 3;
    const int rb = tid >> 4, cb = (tid & 15) << 2;
    const int lm = tid >> 4, d0 = (tid & 15) << 2;

    ull accp[8][2];
    #pragma unroll
    for (int i = 0; i < 8; i++) { accp[i][0] = 0ull; accp[i][1] = 0ull; }

    float4 a1 = *(const float4*)(A + (size_t)lr*MM2 + kq);
    float4 a2 = *(const float4*)(A + (size_t)lr*MM2 + kq + 4);
    float4 b1 = *(const float4*)(Wp + (size_t)rb*64 + cb);

    for (int kt = 0; kt < MM2/16; kt++) {
        __syncthreads();
        As[kq  ][lr] = a1.x; As[kq+1][lr] = a1.y;
        As[kq+2][lr] = a1.z; As[kq+3][lr] = a1.w;
        As[kq+4][lr] = a2.x; As[kq+5][lr] = a2.y;
        As[kq+6][lr] = a2.z; As[kq+7][lr] = a2.w;
        *(float4*)&Bs[rb][cb] = b1;
        __syncthreads();
        if (kt < MM2/16 - 1) {
            a1 = *(const float4*)(A + (size_t)lr*MM2 + (kt+1)*16 + kq);
            a2 = *(const float4*)(A + (size_t)lr*MM2 + (kt+1)*16 + kq + 4);
            b1 = *(const float4*)(Wp + (size_t)((kt+1)*16 + rb)*64 + cb);
        }
        #pragma unroll
        for (int k = 0; k < 16; k++) {
            float4 t0 = *(const float4*)&As[k][lm*8];
            float4 t1 = *(const float4*)&As[k][lm*8+4];
            ulonglong2 bb = *(const ulonglong2*)&Bs[k][d0];
            float a[8] = {t0.x,t0.y,t0.z,t0.w,t1.x,t1.y,t1.z,t1.w};
            #pragma unroll
            for (int i = 0; i < 8; i++) {
                ull ap = bcast2(a[i]);
                ffma2(accp[i][0], ap, bb.x);
                ffma2(accp[i][1], ap, bb.y);
            }
        }
    }
    #pragma unroll
    for (int i = 0; i < 8; i++) {
        float4 v;
        unpk2(accp[i][0], v.x, v.y);
        unpk2(accp[i][1], v.z, v.w);
        *(float4*)(g_oh + (size_t)(b*LSEQ + l0 + lm*8 + i)*HDIM + h*64 + d0) = v;
    }
}

extern "C" void kernel_launch(void* const* d_in, const int* in_sizes, int n_in,
                              void* d_out, int out_size)
{
    const float* x    = (const float*)d_in[0];
    const float* mask = (const float*)d_in[2];
    const float* Wq   = (const float*)d_in[3];
    const float* Wk   = (const float*)d_in[4];
    const float* Wv   = (const float*)d_in[5];
    const float* Wo   = (const float*)d_in[6];
    const float* bo   = (const float*)d_in[7];
    const float* rW   = (const float*)d_in[8];
    const float* rb   = (const float*)d_in[9];
    float* out = (float*)d_out;

    cudaFuncSetAttribute(rff_kernel, cudaFuncAttributeMaxDynamicSharedMemorySize, 66048);
    cudaFuncSetAttribute(chol_solve_kernel, cudaFuncAttributeMaxDynamicSharedMemorySize, 197120);

    qkv_kernel<<<dim3(8, 64, 3), 256>>>(x, Wq, Wk, Wv, mask);
    rff_kernel<<<dim3(64, 16, 2), 256, 66048>>>(rW, rb, mask);
    gram_kernel<<<dim3(2, 2, 64), 256>>>();
    tmat_kernel<<<dim3(2, 64, 4), 256>>>();
    chol_solve_kernel<<<64, 256, 197120>>>();
    outproj_kernel<<<dim3(16, 64), 256>>>();
    final_kernel<<<dim3(8, 64), 256>>>(Wo, bo, mask, out);
}

// round 16
// speedup vs baseline: 1.0621x; 1.0079x over previous
#include <cuda_runtime.h>
#include <math.h>

#define LSEQ 2048
#define HDIM 1024
#define MM2  256
#define RIDGE_C 0.01f

typedef unsigned long long ull;

// ---- packed f32x2 helpers (FFMA2 is PTX-only; ptxas never auto-fuses) ----
__device__ __forceinline__ ull bcast2(float x) {
    ull r; unsigned u = __float_as_uint(x);
    asm("mov.b64 %0, {%1, %1};" : "=l"(r) : "r"(u));
    return r;
}
__device__ __forceinline__ void ffma2(ull& d, ull a, ull b) {
    asm("fma.rn.f32x2 %0, %1, %2, %0;" : "+l"(d) : "l"(a), "l"(b));
}
__device__ __forceinline__ void unpk2(ull v, float& lo, float& hi) {
    unsigned a, b;
    asm("mov.b64 {%0, %1}, %2;" : "=r"(a), "=r"(b) : "l"(v));
    lo = __uint_as_float(a); hi = __uint_as_float(b);
}

// ---- scratch (device globals; no allocations) ----
static __device__ float g_q  [8388608];
static __device__ float g_k  [8388608];
static __device__ float g_v  [8388608];
static __device__ float g_oh [8388608];
static __device__ float g_phiq[33554432];
static __device__ float g_phik[33554432];
static __device__ float g_G  [4194304];
static __device__ float g_Tp [4194304];   // 4 k-split partials of T
static __device__ float g_Wm [1048576];

// ---------------------------------------------------------------
// 128x128 tile NT GEMM: C[8192x1024] = A[8192x1024] * Bt[1024x1024]^T
// double-buffered smem, ONE sync per k-tile, f32x2 accumulators.
// optional bias[1024] and per-row mask[8192] epilogue.
// ---------------------------------------------------------------
__device__ __forceinline__ void gemm_nt_1024(
    const float* __restrict__ A, const float* __restrict__ Bt,
    float* __restrict__ C, const float* __restrict__ bias,
    const float* __restrict__ mask)
{
    __shared__ __align__(16) float As[2][8][132], Bs[2][8][132];
    const int tid = threadIdx.x, bx = blockIdx.x, by = blockIdx.y;
    const int arow = tid >> 1, acol = (tid & 1) << 2;
    const float* Ap = A  + (size_t)(by * 128 + arow) * 1024 + acol;
    const float* Bp = Bt + (size_t)(bx * 128 + arow) * 1024 + acol;
    const int tx = tid & 15, ty = tid >> 4;

    ull accp[8][4];
    #pragma unroll
    for (int i = 0; i < 8; i++)
        #pragma unroll
        for (int j = 0; j < 4; j++) accp[i][j] = 0ull;

    {   // stage tile 0
        float4 av = *(const float4*)Ap;
        float4 bv = *(const float4*)Bp;
        As[0][acol  ][arow] = av.x; As[0][acol+1][arow] = av.y;
        As[0][acol+2][arow] = av.z; As[0][acol+3][arow] = av.w;
        Bs[0][acol  ][arow] = bv.x; Bs[0][acol+1][arow] = bv.y;
        Bs[0][acol+2][arow] = bv.z; Bs[0][acol+3][arow] = bv.w;
    }
    __syncthreads();

    for (int kt = 0; kt < 128; kt++) {
        float4 av, bv;
        const bool more = (kt < 127);
        if (more) {
            av = *(const float4*)(Ap + (size_t)(kt + 1) * 8);
            bv = *(const float4*)(Bp + (size_t)(kt + 1) * 8);
        }
        const int cs = kt & 1;
        #pragma unroll
        for (int k = 0; k < 8; k++) {
            float4 t0 = *(const float4*)&As[cs][k][ty*8];
            float4 t1 = *(const float4*)&As[cs][k][ty*8+4];
            ulonglong2 b0 = *(const ulonglong2*)&Bs[cs][k][tx*8];
            ulonglong2 b1 = *(const ulonglong2*)&Bs[cs][k][tx*8+4];
            float a[8] = {t0.x,t0.y,t0.z,t0.w,t1.x,t1.y,t1.z,t1.w};
            #pragma unroll
            for (int i = 0; i < 8; i++) {
                ull ap = bcast2(a[i]);
                ffma2(accp[i][0], ap, b0.x);
                ffma2(accp[i][1], ap, b0.y);
                ffma2(accp[i][2], ap, b1.x);
                ffma2(accp[i][3], ap, b1.y);
            }
        }
        if (more) {
            const int ns = cs ^ 1;
            As[ns][acol  ][arow] = av.x; As[ns][acol+1][arow] = av.y;
            As[ns][acol+2][arow] = av.z; As[ns][acol+3][arow] = av.w;
            Bs[ns][acol  ][arow] = bv.x; Bs[ns][acol+1][arow] = bv.y;
            Bs[ns][acol+2][arow] = bv.z; Bs[ns][acol+3][arow] = bv.w;
            __syncthreads();
        }
    }

    const int cb0 = bx * 128 + tx * 8;
    #pragma unroll
    for (int i = 0; i < 8; i++) {
        const int row = by * 128 + ty * 8 + i;
        const float mv = mask ? mask[row] : 1.0f;
        float vals[8];
        #pragma unroll
        for (int jp = 0; jp < 4; jp++) unpk2(accp[i][jp], vals[2*jp], vals[2*jp+1]);
        float* Crow = C + (size_t)row * 1024 + cb0;
        #pragma unroll
        for (int j = 0; j < 8; j += 4) {
            float4 v;
            v.x = vals[j]; v.y = vals[j+1]; v.z = vals[j+2]; v.w = vals[j+3];
            if (bias) { v.x += bias[cb0+j]; v.y += bias[cb0+j+1];
                        v.z += bias[cb0+j+2]; v.w += bias[cb0+j+3]; }
            v.x *= mv; v.y *= mv; v.z *= mv; v.w *= mv;
            *(float4*)(Crow + j) = v;
        }
    }
}

__global__ void __launch_bounds__(256) qkv_kernel(
    const float* __restrict__ x, const float* __restrict__ Wq,
    const float* __restrict__ Wk, const float* __restrict__ Wv,
    const float* __restrict__ mask)
{
    const int z = blockIdx.z;
    gemm_nt_1024(x, z==0?Wq:(z==1?Wk:Wv), z==0?g_q:(z==1?g_k:g_v),
                 nullptr, z==2?mask:nullptr);
}

__global__ void __launch_bounds__(256) final_kernel(
    const float* __restrict__ Wo, const float* __restrict__ bo,
    const float* __restrict__ mask, float* __restrict__ out)
{
    gemm_nt_1024(g_oh, Wo, out, bo, mask);
}

// ---------------------------------------------------------------
// RFF: per (bh, 128-row l tile, isK). proj = X(128x64) @ W(64x128) + b
// Phi[:,m]=s*cos, Phi[:,128+m]=s*sin ; PhiK masked per row.
// ---------------------------------------------------------------
__global__ void __launch_bounds__(256) rff_kernel(
    const float* __restrict__ rffW, const float* __restrict__ rffb,
    const float* __restrict__ mask)
{
    extern __shared__ float sm[];
    float* Ws = sm;            // [64][128]
    float* Xs = sm + 8192;     // [128][65]
    __shared__ float bsh[128], msh[128];

    const int bh = blockIdx.x, b = bh >> 4, h = bh & 15;
    const int lt = blockIdx.y, isK = blockIdx.z;
    const float* Xg = (isK ? g_k : g_q) + (size_t)(b*LSEQ + lt*128)*HDIM + h*64;
    float* Phi = (isK ? g_phik : g_phiq) + ((size_t)bh*LSEQ + lt*128)*MM2;

    const int tid = threadIdx.x;
    for (int i = tid; i < 8192; i += 256) Ws[i] = rffW[h*8192 + i];
    if (tid < 128) {
        bsh[tid] = rffb[h*128 + tid];
        msh[tid] = isK ? mask[b*LSEQ + lt*128 + tid] : 1.0f;
    }
    for (int i = tid; i < 8192; i += 256) {
        const int l = i >> 6, d = i & 63;
        Xs[l*65 + d] = Xg[(size_t)l*HDIM + d];
    }
    __syncthreads();

    const int tx = tid & 15, ty = tid >> 4;
    float acc[8][8];
    #pragma unroll
    for (int i = 0; i < 8; i++)
        #pragma unroll
        for (int j = 0; j < 8; j++) acc[i][j] = bsh[tx + 16*j];

    for (int d = 0; d < 64; d++) {
        float a[8], w[8];
        #pragma unroll
        for (int i = 0; i < 8; i++) a[i] = Xs[(ty + 16*i)*65 + d];
        #pragma unroll
        for (int j = 0; j < 8; j++) w[j] = Ws[d*128 + tx + 16*j];
        #pragma unroll
        for (int i = 0; i < 8; i++)
            #pragma unroll
            for (int j = 0; j < 8; j++)
                acc[i][j] = fmaf(a[i], w[j], acc[i][j]);
    }
    const float sc = 0.0883883476483184f;  // 1/sqrt(128)
    #pragma unroll
    for (int i = 0; i < 8; i++) {
        const int l = ty + 16*i;
        const float mv = msh[l];
        float* row = Phi + (size_t)l*MM2;
        #pragma unroll
        for (int j = 0; j < 8; j++) {
            float s, c;
            sincosf(acc[i][j], &s, &c);
            row[tx + 16*j]       = sc * c * mv;
            row[128 + tx + 16*j] = sc * s * mv;
        }
    }
}

// ---------------------------------------------------------------
// Gram: G[bh] = PhiK^T PhiK, 256x256, K=2048. grid (2,2,64)
// double-buffered, one sync per k-tile, f32x2 accumulators.
// ---------------------------------------------------------------
__global__ void __launch_bounds__(256) gram_kernel()
{
    __shared__ __align__(16) float As[2][16][132], Bs[2][16][132];
    const int bh = blockIdx.z;
    const float* A = g_phik + (size_t)bh * LSEQ * MM2;
    const int m0 = blockIdx.y * 128, n0 = blockIdx.x * 128;
    const int tid = threadIdx.x;
    const int r = tid >> 4, c = (tid & 15) << 3;
    const int tx = tid & 15, ty = tid >> 4;

    ull accp[8][4];
    #pragma unroll
    for (int i = 0; i < 8; i++)
        #pragma unroll
        for (int j = 0; j < 4; j++) accp[i][j] = 0ull;

    {
        const float* Arow = A + (size_t)r * MM2;
        *(float4*)&As[0][r][c]   = *(const float4*)(Arow + m0 + c);
        *(float4*)&As[0][r][c+4] = *(const float4*)(Arow + m0 + c + 4);
        *(float4*)&Bs[0][r][c]   = *(const float4*)(Arow + n0 + c);
        *(float4*)&Bs[0][r][c+4] = *(const float4*)(Arow + n0 + c + 4);
    }
    __syncthreads();

    for (int kt = 0; kt < LSEQ/16; kt++) {
        float4 a1, a2, b1, b2;
        const bool more = (kt < LSEQ/16 - 1);
        if (more) {
            const float* An = A + (size_t)((kt+1)*16 + r) * MM2;
            a1 = *(const float4*)(An + m0 + c);
            a2 = *(const float4*)(An + m0 + c + 4);
            b1 = *(const float4*)(An + n0 + c);
            b2 = *(const float4*)(An + n0 + c + 4);
        }
        const int cs = kt & 1;
        #pragma unroll
        for (int k = 0; k < 16; k++) {
            float4 t0 = *(const float4*)&As[cs][k][ty*8];
            float4 t1 = *(const float4*)&As[cs][k][ty*8+4];
            ulonglong2 p0 = *(const ulonglong2*)&Bs[cs][k][tx*8];
            ulonglong2 p1 = *(const ulonglong2*)&Bs[cs][k][tx*8+4];
            float a[8] = {t0.x,t0.y,t0.z,t0.w,t1.x,t1.y,t1.z,t1.w};
            #pragma unroll
            for (int i = 0; i < 8; i++) {
                ull ap = bcast2(a[i]);
                ffma2(accp[i][0], ap, p0.x);
                ffma2(accp[i][1], ap, p0.y);
                ffma2(accp[i][2], ap, p1.x);
                ffma2(accp[i][3], ap, p1.y);
            }
        }
        if (more) {
            const int ns = cs ^ 1;
            *(float4*)&As[ns][r][c]   = a1; *(float4*)&As[ns][r][c+4] = a2;
            *(float4*)&Bs[ns][r][c]   = b1; *(float4*)&Bs[ns][r][c+4] = b2;
            __syncthreads();
        }
    }
    float* Cb = g_G + (size_t)bh * MM2 * MM2;
    #pragma unroll
    for (int i = 0; i < 8; i++) {
        float vals[8];
        #pragma unroll
        for (int jp = 0; jp < 4; jp++) unpk2(accp[i][jp], vals[2*jp], vals[2*jp+1]);
        float* Crow = Cb + (size_t)(m0 + ty*8 + i) * MM2 + n0 + tx*8;
        float4 v0, v1;
        v0.x=vals[0]; v0.y=vals[1]; v0.z=vals[2]; v0.w=vals[3];
        v1.x=vals[4]; v1.y=vals[5]; v1.z=vals[6]; v1.w=vals[7];
        *(float4*)Crow = v0; *(float4*)(Crow+4) = v1;
    }
}

// ---------------------------------------------------------------
// T partials: g_Tp[kz][bh] = PhiK^T V_w over 512-row K chunk.
// grid (2, 64, 4); summed in chol_solve's T load. double-buffered.
// ---------------------------------------------------------------
__global__ void __launch_bounds__(256) tmat_kernel()
{
    __shared__ __align__(16) float As[2][16][132], Bs[2][16][68];
    const int bh = blockIdx.y, b = bh >> 4, h = bh & 15;
    const int m0 = blockIdx.x * 128, kz = blockIdx.z;
    const float* A = g_phik + (size_t)bh * LSEQ * MM2;
    const float* V = g_v + (size_t)b * LSEQ * HDIM + h * 64;
    const int tid = threadIdx.x;
    const int r = tid >> 4, c = (tid & 15) << 3, cb = (tid & 15) << 2;
    const int md = tid >> 4, d0 = (tid & 15) << 2;
    const int kt0 = kz * 32, kt1 = kt0 + 32;

    ull accp[8][2];
    #pragma unroll
    for (int i = 0; i < 8; i++) { accp[i][0] = 0ull; accp[i][1] = 0ull; }

    {
        const float* Ar = A + (size_t)(kt0*16 + r) * MM2 + m0;
        *(float4*)&As[0][r][c]   = *(const float4*)(Ar + c);
        *(float4*)&As[0][r][c+4] = *(const float4*)(Ar + c + 4);
        *(float4*)&Bs[0][r][cb]  = *(const float4*)(V + (size_t)(kt0*16 + r) * HDIM + cb);
    }
    __syncthreads();

    for (int kt = kt0; kt < kt1; kt++) {
        float4 a1, a2, b1;
        const bool more = (kt < kt1 - 1);
        if (more) {
            const float* An = A + (size_t)((kt+1)*16 + r) * MM2 + m0;
            a1 = *(const float4*)(An + c);
            a2 = *(const float4*)(An + c + 4);
            b1 = *(const float4*)(V + (size_t)((kt+1)*16 + r) * HDIM + cb);
        }
        const int cs = kt & 1;
        #pragma unroll
        for (int k = 0; k < 16; k++) {
            float4 t0 = *(const float4*)&As[cs][k][md*8];
            float4 t1 = *(const float4*)&As[cs][k][md*8+4];
            ulonglong2 bb = *(const ulonglong2*)&Bs[cs][k][d0];
            float a[8] = {t0.x,t0.y,t0.z,t0.w,t1.x,t1.y,t1.z,t1.w};
            #pragma unroll
            for (int i = 0; i < 8; i++) {
                ull ap = bcast2(a[i]);
                ffma2(accp[i][0], ap, bb.x);
                ffma2(accp[i][1], ap, bb.y);
            }
        }
        if (more) {
            const int ns = cs ^ 1;
            *(float4*)&As[ns][r][c]   = a1; *(float4*)&As[ns][r][c+4] = a2;
            *(float4*)&Bs[ns][r][cb]  = b1;
            __syncthreads();
        }
    }
    float* C = g_Tp + (size_t)kz * 1048576 + (size_t)bh * 16384;
    #pragma unroll
    for (int i = 0; i < 8; i++) {
        float4 v;
        unpk2(accp[i][0], v.x, v.y);
        unpk2(accp[i][1], v.z, v.w);
        *(float4*)(C + (size_t)(m0 + md*8 + i) * 64 + d0) = v;
    }
}

// ---------------------------------------------------------------
// Per-(b,h): Cholesky (packed lower in smem) + L y = T, L^T x = y (64 RHS).
// dyn smem = 32896*4 + 16384*4 = 197120 B. grid 64.
// ---------------------------------------------------------------
__global__ void __launch_bounds__(256) chol_solve_kernel()
{
    extern __shared__ float sm[];
    float* Lp = sm;            // packed lower: Lp[i*(i+1)/2 + j]
    float* Y  = sm + 32896;    // [256][64]
    __shared__ float sdiag, sinv;
    const int bh = blockIdx.x, tid = threadIdx.x;
    const float* G  = g_G + (size_t)bh * 65536;
    const float* T0 = g_Tp + (size_t)bh * 16384;

    for (int i = 0; i < 256; i++) {
        const int ro = i*(i+1)/2;
        for (int j = tid; j <= i; j += 256)
            Lp[ro + j] = G[i*256 + j] + ((j == i) ? RIDGE_C : 0.0f);
    }
    for (int t = tid; t < 16384; t += 256)
        Y[t] = (T0[t] + T0[t + 1048576]) + (T0[t + 2097152] + T0[t + 3145728]);
    __syncthreads();

    // left-looking Cholesky, column j; thread tid owns row j+tid
    for (int j = 0; j < 256; j++) {
        const int r = j + tid, jo = j*(j+1)/2;
        float a = 0.0f; int ro = 0;
        if (r < 256) {
            ro = r*(r+1)/2;
            float a0=0.f, a1=0.f, a2=0.f, a3=0.f; int c = 0;
            for (; c + 4 <= j; c += 4) {
                a0 = fmaf(Lp[ro+c  ], Lp[jo+c  ], a0);
                a1 = fmaf(Lp[ro+c+1], Lp[jo+c+1], a1);
                a2 = fmaf(Lp[ro+c+2], Lp[jo+c+2], a2);
                a3 = fmaf(Lp[ro+c+3], Lp[jo+c+3], a3);
            }
            for (; c < j; c++) a0 = fmaf(Lp[ro+c], Lp[jo+c], a0);
            a = Lp[ro + j] - ((a0 + a1) + (a2 + a3));
        }
        if (tid == 0) { float s = sqrtf(a); sdiag = s; sinv = 1.0f / s; }
        __syncthreads();
        if (r < 256) Lp[ro + j] = (tid == 0) ? sdiag : a * sinv;
        __syncthreads();
    }

    const int d = tid & 63, io = tid >> 6;
    // forward: L y = T (8-col blocked)
    for (int jb = 0; jb < 256; jb += 8) {
        for (int jj = 0; jj < 8; jj++) {
            const int j = jb + jj;
            if (tid < 64) {
                const int jo = j*(j+1)/2;
                float yv = Y[j*64 + tid];
                for (int c = jb; c < j; c++)
                    yv = fmaf(-Lp[jo + c], Y[c*64 + tid], yv);
                Y[j*64 + tid] = yv / Lp[jo + j];
            }
            __syncthreads();
        }
        for (int i = jb + 8 + io; i < 256; i += 4) {
            const int ro = i*(i+1)/2 + jb;
            float a = Y[i*64 + d];
            #pragma unroll
            for (int jj = 0; jj < 8; jj++)
                a = fmaf(-Lp[ro + jj], Y[(jb+jj)*64 + d], a);
            Y[i*64 + d] = a;
        }
        __syncthreads();
    }
    // backward: L^T x = y (8-row blocked, bottom-up)
    for (int ib = 248; ib >= 0; ib -= 8) {
        for (int jj = 7; jj >= 0; jj--) {
            const int j = ib + jj;
            if (tid < 64) {
                float yv = Y[j*64 + tid];
                for (int c = j + 1; c < ib + 8; c++)
                    yv = fmaf(-Lp[c*(c+1)/2 + j], Y[c*64 + tid], yv);
                Y[j*64 + tid] = yv / Lp[j*(j+1)/2 + j];
            }
            __syncthreads();
        }
        for (int i = io; i < ib; i += 4) {
            float a = Y[i*64 + d];
            #pragma unroll
            for (int jj = 0; jj < 8; jj++) {
                const int k = ib + jj;
                a = fmaf(-Lp[k*(k+1)/2 + i], Y[k*64 + d], a);
            }
            Y[i*64 + d] = a;
        }
        __syncthreads();
    }
    float* Wout = g_Wm + (size_t)bh * 16384;
    for (int t = tid; t < 16384; t += 256) Wout[t] = Y[t];
}

// ---------------------------------------------------------------
// out_heads = PhiQ(2048x256) @ W(256x64) per bh -> g_oh[(b,l),(h*64+d)]
// grid (16, 64). double-buffered, f32x2 accumulators.
// ---------------------------------------------------------------
__global__ void __launch_bounds__(256) outproj_kernel()
{
    __shared__ __align__(16) float As[2][16][132], Bs[2][16][68];
    const int bh = blockIdx.y, b = bh >> 4, h = bh & 15;
    const int l0 = blockIdx.x * 128;
    const float* A  = g_phiq + ((size_t)bh*LSEQ + l0) * MM2;
    const float* Wp = g_Wm + (size_t)bh * 16384;
    const int tid = threadIdx.x;
    const int lr = tid >> 1, kq = (tid & 1) << 3;
    const int rb = tid >> 4, cb = (tid & 15) << 2;
    const int lm = tid >> 4, d0 = (tid & 15) << 2;

    ull accp[8][2];
    #pragma unroll
    for (int i = 0; i < 8; i++) { accp[i][0] = 0ull; accp[i][1] = 0ull; }

    {
        float4 a1 = *(const float4*)(A + (size_t)lr*MM2 + kq);
        float4 a2 = *(const float4*)(A + (size_t)lr*MM2 + kq + 4);
        As[0][kq  ][lr] = a1.x; As[0][kq+1][lr] = a1.y;
        As[0][kq+2][lr] = a1.z; As[0][kq+3][lr] = a1.w;
        As[0][kq+4][lr] = a2.x; As[0][kq+5][lr] = a2.y;
        As[0][kq+6][lr] = a2.z; As[0][kq+7][lr] = a2.w;
        *(float4*)&Bs[0][rb][cb] = *(const float4*)(Wp + (size_t)rb*64 + cb);
    }
    __syncthreads();

    for (int kt = 0; kt < MM2/16; kt++) {
        float4 a1, a2, b1;
        const bool more = (kt < MM2/16 - 1);
        if (more) {
            a1 = *(const float4*)(A + (size_t)lr*MM2 + (kt+1)*16 + kq);
            a2 = *(const float4*)(A + (size_t)lr*MM2 + (kt+1)*16 + kq + 4);
            b1 = *(const float4*)(Wp + (size_t)((kt+1)*16 + rb)*64 + cb);
        }
        const int cs = kt & 1;
        #pragma unroll
        for (int k = 0; k < 16; k++) {
            float4 t0 = *(const float4*)&As[cs][k][lm*8];
            float4 t1 = *(const float4*)&As[cs][k][lm*8+4];
            ulonglong2 bb = *(const ulonglong2*)&Bs[cs][k][d0];
            float a[8] = {t0.x,t0.y,t0.z,t0.w,t1.x,t1.y,t1.z,t1.w};
            #pragma unroll
            for (int i = 0; i < 8; i++) {
                ull ap = bcast2(a[i]);
                ffma2(accp[i][0], ap, bb.x);
                ffma2(accp[i][1], ap, bb.y);
            }
        }
        if (more) {
            const int ns = cs ^ 1;
            As[ns][kq  ][lr] = a1.x; As[ns][kq+1][lr] = a1.y;
            As[ns][kq+2][lr] = a1.z; As[ns][kq+3][lr] = a1.w;
            As[ns][kq+4][lr] = a2.x; As[ns][kq+5][lr] = a2.y;
            As[ns][kq+6][lr] = a2.z; As[ns][kq+7][lr] = a2.w;
            *(float4*)&Bs[ns][rb][cb] = b1;
            __syncthreads();
        }
    }
    #pragma unroll
    for (int i = 0; i < 8; i++) {
        float4 v;
        unpk2(accp[i][0], v.x, v.y);
        unpk2(accp[i][1], v.z, v.w);
        *(float4*)(g_oh + (size_t)(b*LSEQ + l0 + lm*8 + i)*HDIM + h*64 + d0) = v;
    }
}

extern "C" void kernel_launch(void* const* d_in, const int* in_sizes, int n_in,
                              void* d_out, int out_size)
{
    const float* x    = (const float*)d_in[0];
    const float* mask = (const float*)d_in[2];
    const float* Wq   = (const float*)d_in[3];
    const float* Wk   = (const float*)d_in[4];
    const float* Wv   = (const float*)d_in[5];
    const float* Wo   = (const float*)d_in[6];
    const float* bo   = (const float*)d_in[7];
    const float* rW   = (const float*)d_in[8];
    const float* rb   = (const float*)d_in[9];
    float* out = (float*)d_out;

    cudaFuncSetAttribute(rff_kernel, cudaFuncAttributeMaxDynamicSharedMemorySize, 66048);
    cudaFuncSetAttribute(chol_solve_kernel, cudaFuncAttributeMaxDynamicSharedMemorySize, 197120);

    qkv_kernel<<<dim3(8, 64, 3), 256>>>(x, Wq, Wk, Wv, mask);
    rff_kernel<<<dim3(64, 16, 2), 256, 66048>>>(rW, rb, mask);
    gram_kernel<<<dim3(2, 2, 64), 256>>>();
    tmat_kernel<<<dim3(2, 64, 4), 256>>>();
    chol_solve_kernel<<<64, 256, 197120>>>();
    outproj_kernel<<<dim3(16, 64), 256>>>();
    final_kernel<<<dim3(8, 64), 256>>>(Wo, bo, mask, out);
}